// round 1
// baseline (speedup 1.0000x reference)
#include <cuda_runtime.h>
#include <math.h>

namespace {
constexpr int kBn = 2, kS = 1024, kD = 1024, kH = 16, kDH = 64, kL = 4;
constexpr int kBS = kBn * kS;          // 2048 rows
constexpr int kBH = kBn * kH;          // 32 (b,h) pairs
constexpr int TR = 32;                 // query rows per attention block
constexpr int NTILES = kS / TR;        // 32
constexpr int ATTN_THREADS = 512;      // 16 warps
constexpr int ATTN_SMEM_FLOATS = TR * kS + 2 * TR * 65;
constexpr int ATTN_SMEM_BYTES = ATTN_SMEM_FLOATS * 4;  // 147712 B
}

// Scratch (static device allocations; no runtime allocs)
__device__ float g_x[kBS * kD];            // current activations (B,S,D)
__device__ float g_qh[kBH * kS * kDH];     // q heads (B,H,S,DH) -- also used as k
__device__ float g_vh[kBH * kS * kDH];     // v heads (B,H,S,DH)
__device__ float g_ao[kBS * kD];           // attention output (B,S,D)
__device__ float g_proj[kBS * kD];         // Wo projection result

// ---------------------------------------------------------------------------
__global__ void copy_k(const float* __restrict__ in) {
    int i = blockIdx.x * blockDim.x + threadIdx.x;
    reinterpret_cast<float4*>(g_x)[i] = reinterpret_cast<const float4*>(in)[i];
}

// ---------------------------------------------------------------------------
// C[M=2048, N=1024] = A[M,K=1024] @ W[K,N] + bias[N]
// SCATTER: write element (m=b*S+s, n=h*64+d) to (B,H,S,DH) layout.
template<bool SCATTER>
__global__ void __launch_bounds__(256) gemm_k(const float* __restrict__ A,
                                              const float* __restrict__ W,
                                              const float* __restrict__ bias,
                                              float* __restrict__ C) {
    __shared__ __align__(16) float As[16][65];   // [k][m], padded stride
    __shared__ __align__(16) float Bs[16][64];   // [k][n]
    const int tid = threadIdx.x;
    const int tx = tid & 15, ty = tid >> 4;
    const int mbase = blockIdx.y * 64, nbase = blockIdx.x * 64;
    const int am = tid >> 2, ak = (tid & 3) << 2;    // A loader: row am, k4 block ak
    const int bk = tid >> 4, bn = (tid & 15) << 2;   // B loader: k row bk, n4 block bn
    float acc[4][4] = {};
    for (int kt = 0; kt < kD; kt += 16) {
        float4 av = *reinterpret_cast<const float4*>(A + (size_t)(mbase + am) * kD + kt + ak);
        float4 bv = *reinterpret_cast<const float4*>(W + (size_t)(kt + bk) * kD + nbase + bn);
        As[ak + 0][am] = av.x;
        As[ak + 1][am] = av.y;
        As[ak + 2][am] = av.z;
        As[ak + 3][am] = av.w;
        *reinterpret_cast<float4*>(&Bs[bk][bn]) = bv;
        __syncthreads();
        #pragma unroll
        for (int k = 0; k < 16; k++) {
            float a[4];
            #pragma unroll
            for (int r = 0; r < 4; r++) a[r] = As[k][ty * 4 + r];
            float4 b4 = *reinterpret_cast<float4*>(&Bs[k][tx * 4]);
            float bb[4] = {b4.x, b4.y, b4.z, b4.w};
            #pragma unroll
            for (int r = 0; r < 4; r++)
                #pragma unroll
                for (int c = 0; c < 4; c++)
                    acc[r][c] += a[r] * bb[c];
        }
        __syncthreads();
    }
    #pragma unroll
    for (int r = 0; r < 4; r++) {
        int m = mbase + ty * 4 + r;
        int b = m / kS, s = m - b * kS;
        #pragma unroll
        for (int c = 0; c < 4; c++) {
            int n = nbase + tx * 4 + c;
            float v = acc[r][c] + bias[n];
            if (SCATTER) {
                int h = n >> 6, d = n & 63;
                C[(((size_t)b * kH + h) * kS + s) * kDH + d] = v;
            } else {
                C[(size_t)m * kD + n] = v;
            }
        }
    }
}

// ---------------------------------------------------------------------------
// Gamma attention. One block per (b, h, 32-row tile). Full score rows live in
// smem so the sequential cumsum/decay path is exact. kq_same: keys == q proj.
__global__ void __launch_bounds__(ATTN_THREADS) attn_k(const float* __restrict__ gam) {
    extern __shared__ float smem[];
    float* sc  = smem;                 // TR * kS score rows
    float* sq  = sc + TR * kS;         // TR * 65 query tile (padded)
    float* skv = sq + TR * 65;         // TR * 65 key/value tile (padded)

    const int bx = blockIdx.x;
    const int tile = bx & (NTILES - 1);
    const int h = (bx / NTILES) & (kH - 1);
    const int b = bx / (NTILES * kH);
    const int bh = b * kH + h;
    const int base = tile * TR;
    const int tid = threadIdx.x;
    const int lane = tid & 31;
    const int w = tid >> 5;            // warp 0..15

    const float* qbase = g_qh + (size_t)bh * kS * kDH;
    const float* vbase = g_vh + (size_t)bh * kS * kDH;

    // load query tile
    for (int idx = tid; idx < TR * kDH; idx += ATTN_THREADS) {
        int r = idx >> 6, d = idx & 63;
        sq[r * 65 + d] = qbase[(size_t)(base + r) * kDH + d];
    }
    __syncthreads();

    const int nkt = tile + 1;          // key tiles covering [0, base+32)
    const int kLimit = nkt * TR;
    const int r0 = 2 * w, r1 = 2 * w + 1;

    // ---- Phase 1: scores = (q_i . q_j) / sqrt(DH) ----
    for (int kt = 0; kt < nkt; kt++) {
        const int j0 = kt * TR;
        for (int idx = tid; idx < TR * kDH; idx += ATTN_THREADS) {
            int r = idx >> 6, d = idx & 63;
            skv[r * 65 + d] = qbase[(size_t)(j0 + r) * kDH + d];
        }
        __syncthreads();
        float a0 = 0.f, a1 = 0.f;
        const float* kc = skv + lane * 65;  // lane = key; conflict-free (pad 65)
        const float* q0 = sq + r0 * 65;
        const float* q1 = sq + r1 * 65;
        #pragma unroll
        for (int d = 0; d < kDH; d++) {
            float kv = kc[d];
            a0 += q0[d] * kv;
            a1 += q1[d] * kv;
        }
        sc[r0 * kS + j0 + lane] = a0 * 0.125f;
        sc[r1 * kS + j0 + lane] = a1 * 0.125f;
        __syncthreads();
    }

    // ---- Phase 2: per-row softmax -> cumsum decay -> softmax -> maxout ----
    const float gm = -fabsf(gam[h]);
    #pragma unroll
    for (int rr = 0; rr < 2; rr++) {
        const int r = w + rr * 16;     // interleave rows across warps for balance
        const int i = base + r;
        const int nv = i;              // strict causal: keys j < i
        float* row = sc + (size_t)r * kS;
        if (nv == 0) {                 // row 0: attn == 0 exactly
            for (int j = lane; j < kLimit; j += 32) row[j] = 0.f;
            continue;
        }
        // softmax 1 stats
        float mx = -3.4e38f;
        for (int j = lane; j < nv; j += 32) mx = fmaxf(mx, row[j]);
        #pragma unroll
        for (int o = 16; o; o >>= 1) mx = fmaxf(mx, __shfl_xor_sync(0xffffffffu, mx, o));
        float sum = 0.f;
        for (int j = lane; j < nv; j += 32) sum += __expf(row[j] - mx);
        #pragma unroll
        for (int o = 16; o; o >>= 1) sum += __shfl_xor_sync(0xffffffffu, sum, o);
        const float inv = 1.0f / sum;
        // sequential (chunked warp-scan) cumsum of p, apply distance decay in place
        float carry = 0.f;
        for (int c0 = 0; c0 < nv; c0 += 32) {
            int j = c0 + lane;
            bool valid = j < nv;
            float sv = valid ? row[j] : 0.f;
            float p = valid ? __expf(sv - mx) * inv : 0.f;
            #pragma unroll
            for (int o = 1; o < 32; o <<= 1) {
                float t = __shfl_up_sync(0xffffffffu, p, o);
                if (lane >= o) p += t;
            }
            float cum = p + carry;
            float nc = __shfl_sync(0xffffffffu, cum, 31);
            if (valid) {
                float rem = 1.0f - cum;                 // disttotal == 1
                float tt = fmaxf(rem * (float)(i - j), 0.f);
                float dist = sqrtf(tt);
                float eff = fmaxf(__expf(gm * dist), 1e-5f);  // exp<=1, only low clamp binds
                row[j] = sv * eff;
            }
            carry = nc;
        }
        // softmax 2 + maxout: max(attn) = 1/sum2, so scale = min(sum2,5)/sum2
        float mx2 = -3.4e38f;
        for (int j = lane; j < nv; j += 32) mx2 = fmaxf(mx2, row[j]);
        #pragma unroll
        for (int o = 16; o; o >>= 1) mx2 = fmaxf(mx2, __shfl_xor_sync(0xffffffffu, mx2, o));
        float sum2 = 0.f;
        for (int j = lane; j < nv; j += 32) sum2 += __expf(row[j] - mx2);
        #pragma unroll
        for (int o = 16; o; o >>= 1) sum2 += __shfl_xor_sync(0xffffffffu, sum2, o);
        const float sfac = fminf(sum2, 5.0f) / sum2;
        for (int j = lane; j < nv; j += 32) row[j] = __expf(row[j] - mx2) * sfac;
        for (int j = nv + lane; j < kLimit; j += 32) row[j] = 0.f;
    }
    __syncthreads();

    // ---- Phase 3: out = attn @ V ----
    float o00 = 0.f, o01 = 0.f, o10 = 0.f, o11 = 0.f;
    for (int kt = 0; kt < nkt; kt++) {
        const int j0 = kt * TR;
        for (int idx = tid; idx < TR * kDH; idx += ATTN_THREADS) {
            int r = idx >> 6, d = idx & 63;
            skv[r * 65 + d] = vbase[(size_t)(j0 + r) * kDH + d];
        }
        __syncthreads();
        #pragma unroll 8
        for (int kk = 0; kk < TR; kk++) {
            float v0 = skv[kk * 65 + lane];
            float v1 = skv[kk * 65 + 32 + lane];
            float a0 = sc[(size_t)r0 * kS + j0 + kk];   // smem broadcast
            float a1 = sc[(size_t)r1 * kS + j0 + kk];
            o00 += a0 * v0; o01 += a0 * v1;
            o10 += a1 * v0; o11 += a1 * v1;
        }
        __syncthreads();
    }
    {
        const int i0 = base + r0, i1 = base + r1;
        float* op0 = g_ao + ((size_t)b * kS + i0) * kD + h * kDH;
        op0[lane] = o00; op0[32 + lane] = o01;
        float* op1 = g_ao + ((size_t)b * kS + i1) * kD + h * kDH;
        op1[lane] = o10; op1[32 + lane] = o11;
    }
}

// ---------------------------------------------------------------------------
// out[row] = LayerNorm(X[row] (+ Aadd[row])) * g + b ; one block per row.
template<bool ADD>
__global__ void __launch_bounds__(256) ln_k(const float* __restrict__ X,
                                            const float* __restrict__ Aadd,
                                            const float* __restrict__ g,
                                            const float* __restrict__ bt,
                                            float* __restrict__ out) {
    __shared__ float red[8];
    const int row = blockIdx.x;
    const int tid = threadIdx.x;
    const int lane = tid & 31, w = tid >> 5;
    const float* xr = X + (size_t)row * kD;
    float v[4];
    float s = 0.f;
    #pragma unroll
    for (int t = 0; t < 4; t++) {
        int d = tid + t * 256;
        float val = xr[d];
        if (ADD) val += Aadd[(size_t)row * kD + d];
        v[t] = val;
        s += val;
    }
    #pragma unroll
    for (int o = 16; o; o >>= 1) s += __shfl_xor_sync(0xffffffffu, s, o);
    if (lane == 0) red[w] = s;
    __syncthreads();
    float tot = 0.f;
    #pragma unroll
    for (int k = 0; k < 8; k++) tot += red[k];
    const float mu = tot * (1.0f / kD);
    __syncthreads();
    float s2 = 0.f;
    #pragma unroll
    for (int t = 0; t < 4; t++) { float dv = v[t] - mu; s2 += dv * dv; }
    #pragma unroll
    for (int o = 16; o; o >>= 1) s2 += __shfl_xor_sync(0xffffffffu, s2, o);
    if (lane == 0) red[w] = s2;
    __syncthreads();
    float tot2 = 0.f;
    #pragma unroll
    for (int k = 0; k < 8; k++) tot2 += red[k];
    const float rs = rsqrtf(tot2 * (1.0f / kD) + 1e-5f);
    #pragma unroll
    for (int t = 0; t < 4; t++) {
        int d = tid + t * 256;
        out[(size_t)row * kD + d] = (v[t] - mu) * rs * g[d] + bt[d];
    }
}

// ---------------------------------------------------------------------------
extern "C" void kernel_launch(void* const* d_in, const int* in_sizes, int n_in,
                              void* d_out, int out_size) {
    (void)in_sizes; (void)n_in; (void)out_size;
    const float* q   = (const float*)d_in[0];
    // d_in[1] = lens (unused in eval mode)
    const float* Wq  = (const float*)d_in[2];
    const float* bq  = (const float*)d_in[3];
    const float* Wv  = (const float*)d_in[4];
    const float* bv  = (const float*)d_in[5];
    const float* Wo  = (const float*)d_in[6];
    const float* bo  = (const float*)d_in[7];
    const float* gm  = (const float*)d_in[8];
    const float* lng = (const float*)d_in[9];
    const float* lnb = (const float*)d_in[10];
    const float* fg  = (const float*)d_in[11];
    const float* fb  = (const float*)d_in[12];
    float* out = (float*)d_out;

    cudaFuncSetAttribute(attn_k, cudaFuncAttributeMaxDynamicSharedMemorySize,
                         ATTN_SMEM_BYTES);

    void* p;
    float *xg, *qhg, *vhg, *aog, *pjg;
    cudaGetSymbolAddress(&p, g_x);    xg  = (float*)p;
    cudaGetSymbolAddress(&p, g_qh);   qhg = (float*)p;
    cudaGetSymbolAddress(&p, g_vh);   vhg = (float*)p;
    cudaGetSymbolAddress(&p, g_ao);   aog = (float*)p;
    cudaGetSymbolAddress(&p, g_proj); pjg = (float*)p;

    copy_k<<<(kBS * kD / 4) / 256, 256>>>(q);

    dim3 ggrid(kD / 64, kBS / 64);
    for (int l = 0; l < kL; l++) {
        gemm_k<true ><<<ggrid, 256>>>(xg,  Wq + (size_t)l * kD * kD, bq + l * kD, qhg);
        gemm_k<true ><<<ggrid, 256>>>(xg,  Wv + (size_t)l * kD * kD, bv + l * kD, vhg);
        attn_k<<<kBH * NTILES, ATTN_THREADS, ATTN_SMEM_BYTES>>>(gm + l * kH);
        gemm_k<false><<<ggrid, 256>>>(aog, Wo + (size_t)l * kD * kD, bo + l * kD, pjg);
        ln_k<true ><<<kBS, 256>>>(xg, pjg, lng + l * kD, lnb + l * kD, xg);
    }
    ln_k<false><<<kBS, 256>>>(xg, nullptr, fg, fb, out);
}

// round 3
// speedup vs baseline: 2.7559x; 2.7559x over previous
#include <cuda_runtime.h>
#include <math.h>
#include <stdint.h>

namespace {
constexpr int kBn = 2, kS = 1024, kD = 1024, kH = 16, kDH = 64, kL = 4;
constexpr int kBS = kBn * kS;          // 2048 rows
constexpr int kBH = kBn * kH;          // 32 (b,h) pairs
constexpr int TR = 32;                 // query rows per attention block
constexpr int NTILES = kS / TR;        // 32
constexpr int SCP = 1036;              // padded score-row stride (floats)
constexpr int ATTN_THREADS = 512;      // 16 warps
constexpr int RED_FLOATS = TR * kDH;   // 2048 phase-3 partial buffer
constexpr int ATTN_SMEM = (TR * SCP + RED_FLOATS) * 4;   // 140800 B
// GEMM tiling
constexpr int BM = 128, BN = 128, BK = 32;
constexpr int ASTR = 36, BSTR = 136;   // padded smem strides
constexpr int GEMM_SMEM = (2 * BM * ASTR + 2 * BK * BSTR) * 4;  // 71680 B
}

// Scratch (static device allocations; no runtime allocs)
__device__ float g_x[kBS * kD];
__device__ float g_qh[kBH * kS * kDH];
__device__ float g_vh[kBH * kS * kDH];
__device__ float g_ao[kBS * kD];
__device__ float g_proj[kBS * kD];

// ---------------------------------------------------------------------------
__device__ __forceinline__ uint32_t f2tf(float x) {
    uint32_t r;
    asm("cvt.rna.tf32.f32 %0, %1;" : "=r"(r) : "f"(x));
    return r;
}
__device__ __forceinline__ void mma8(float* d, const uint32_t* a, const uint32_t* b) {
    asm volatile(
        "mma.sync.aligned.m16n8k8.row.col.f32.tf32.tf32.f32 "
        "{%0,%1,%2,%3}, {%4,%5,%6,%7}, {%8,%9}, {%0,%1,%2,%3};\n"
        : "+f"(d[0]), "+f"(d[1]), "+f"(d[2]), "+f"(d[3])
        : "r"(a[0]), "r"(a[1]), "r"(a[2]), "r"(a[3]), "r"(b[0]), "r"(b[1]));
}

// ---------------------------------------------------------------------------
__global__ void copy_k(const float* __restrict__ in) {
    int i = blockIdx.x * blockDim.x + threadIdx.x;
    reinterpret_cast<float4*>(g_x)[i] = reinterpret_cast<const float4*>(in)[i];
}

// ---------------------------------------------------------------------------
// C[2048,1024] = A @ W + bias, tf32 tensor cores, cp.async double buffering.
// Block 128x128, 8 warps of 32x64. SCATTER writes (B,H,S,DH) layout.
template<bool SCATTER>
__global__ void __launch_bounds__(256) gemm_tf32(const float* __restrict__ A,
                                                 const float* __restrict__ W,
                                                 const float* __restrict__ bias,
                                                 float* __restrict__ C) {
    extern __shared__ float sm[];
    float* As = sm;                       // 2 * BM*ASTR
    float* Bs = sm + 2 * BM * ASTR;       // 2 * BK*BSTR
    const int tid = threadIdx.x, lane = tid & 31, w = tid >> 5;
    const int gid = lane >> 2, l4 = lane & 3;
    const int warpM = w & 3, warpN = w >> 2;
    const int mbase = blockIdx.y * BM, nbase = blockIdx.x * BN;
    const uint32_t sA = (uint32_t)__cvta_generic_to_shared(As);
    const uint32_t sB = (uint32_t)__cvta_generic_to_shared(Bs);

    auto prefetch = [&](int kt, int buf) {
        #pragma unroll
        for (int i = 0; i < 4; i++) {
            int cid = tid + i * 256;
            int m = cid >> 3, kc = cid & 7;
            uint32_t dst = sA + (uint32_t)((buf * BM * ASTR + m * ASTR + kc * 4) * 4);
            const float* src = A + (size_t)(mbase + m) * kD + kt * BK + kc * 4;
            asm volatile("cp.async.cg.shared.global [%0], [%1], 16;\n" ::"r"(dst), "l"(src));
        }
        #pragma unroll
        for (int i = 0; i < 4; i++) {
            int cid = tid + i * 256;
            int k = cid >> 5, nc = cid & 31;   // full 32 x 128 tile
            uint32_t dst = sB + (uint32_t)((buf * BK * BSTR + k * BSTR + nc * 4) * 4);
            const float* src = W + (size_t)(kt * BK + k) * kD + nbase + nc * 4;
            asm volatile("cp.async.cg.shared.global [%0], [%1], 16;\n" ::"r"(dst), "l"(src));
        }
        asm volatile("cp.async.commit_group;\n");
    };

    float acc[2][8][4] = {};
    prefetch(0, 0);
    const int nK = kD / BK;
    for (int kt = 0; kt < nK; kt++) {
        asm volatile("cp.async.wait_group 0;\n");
        __syncthreads();
        if (kt + 1 < nK) prefetch(kt + 1, (kt + 1) & 1);
        const float* as = As + (kt & 1) * BM * ASTR;
        const float* bs = Bs + (kt & 1) * BK * BSTR;
        #pragma unroll
        for (int ks = 0; ks < 4; ks++) {
            uint32_t af[2][4];
            #pragma unroll
            for (int mt = 0; mt < 2; mt++) {
                int r = warpM * 32 + mt * 16 + gid;
                const float* p = as + r * ASTR + ks * 8 + l4;
                af[mt][0] = f2tf(p[0]);
                af[mt][1] = f2tf(p[8 * ASTR]);
                af[mt][2] = f2tf(p[4]);
                af[mt][3] = f2tf(p[8 * ASTR + 4]);
            }
            #pragma unroll
            for (int nt = 0; nt < 8; nt++) {
                uint32_t bf[2];
                int cn = warpN * 64 + nt * 8 + gid;
                const float* p = bs + (ks * 8 + l4) * BSTR + cn;
                bf[0] = f2tf(p[0]);
                bf[1] = f2tf(p[4 * BSTR]);
                #pragma unroll
                for (int mt = 0; mt < 2; mt++) mma8(acc[mt][nt], af[mt], bf);
            }
        }
        __syncthreads();
    }
    #pragma unroll
    for (int mt = 0; mt < 2; mt++) {
        int r0 = mbase + warpM * 32 + mt * 16 + gid;
        #pragma unroll
        for (int nt = 0; nt < 8; nt++) {
            int cc = nbase + warpN * 64 + nt * 8 + l4 * 2;
            float b0 = bias[cc], b1 = bias[cc + 1];
            float2 u = make_float2(acc[mt][nt][0] + b0, acc[mt][nt][1] + b1);
            float2 v = make_float2(acc[mt][nt][2] + b0, acc[mt][nt][3] + b1);
            if (SCATTER) {
                int bb = r0 / kS, s = r0 - bb * kS;
                int h = cc >> 6, d = cc & 63;
                *(float2*)&C[(((size_t)bb * kH + h) * kS + s) * kDH + d] = u;
                *(float2*)&C[(((size_t)bb * kH + h) * kS + s + 8) * kDH + d] = v;
            } else {
                *(float2*)&C[(size_t)r0 * kD + cc] = u;
                *(float2*)&C[(size_t)(r0 + 8) * kD + cc] = v;
            }
        }
    }
}

// ---------------------------------------------------------------------------
// Gamma attention with tf32 mma for QK^T and attn@V; exact serial decay path
// on full score rows held in smem. One block per (b,h,32-row query tile).
__global__ void __launch_bounds__(ATTN_THREADS) attn_k(const float* __restrict__ gam) {
    extern __shared__ float sc[];                 // [TR][SCP] scores
    float* red = sc + TR * SCP;                   // [TR][64] phase-3 partials

    const int bx = blockIdx.x;
    const int tile = bx & (NTILES - 1);
    const int h = (bx / NTILES) & (kH - 1);
    const int b = bx / (NTILES * kH);
    const int bh = b * kH + h;
    const int base = tile * TR;
    const int tid = threadIdx.x, lane = tid & 31, w = tid >> 5;
    const int gid = lane >> 2, l4 = lane & 3;
    const float* qb = g_qh + (size_t)bh * kS * kDH;
    const float* vb = g_vh + (size_t)bh * kS * kDH;
    const int nkt = tile + 1, kLimit = nkt * TR;

    // ---- Phase 1: scores = QK^T / 8 via tf32 mma, warps parallel over key tiles
    for (int kt = w; kt < nkt; kt += 16) {
        const float* kp = qb + (size_t)kt * TR * kDH;
        float acc[2][4][4] = {};
        #pragma unroll
        for (int ks = 0; ks < 8; ks++) {
            uint32_t qa[2][4];
            #pragma unroll
            for (int mt = 0; mt < 2; mt++) {
                const float* p = qb + (size_t)(base + mt * 16 + gid) * kDH + ks * 8 + l4;
                qa[mt][0] = f2tf(p[0]);
                qa[mt][1] = f2tf(p[8 * kDH]);
                qa[mt][2] = f2tf(p[4]);
                qa[mt][3] = f2tf(p[8 * kDH + 4]);
            }
            uint32_t bf[4][2];
            #pragma unroll
            for (int nt = 0; nt < 4; nt++) {
                const float* p = kp + (size_t)(nt * 8 + gid) * kDH + ks * 8 + l4;
                bf[nt][0] = f2tf(p[0]);
                bf[nt][1] = f2tf(p[4]);
            }
            #pragma unroll
            for (int mt = 0; mt < 2; mt++)
                #pragma unroll
                for (int nt = 0; nt < 4; nt++) mma8(acc[mt][nt], qa[mt], bf[nt]);
        }
        #pragma unroll
        for (int mt = 0; mt < 2; mt++) {
            int rl = mt * 16 + gid;
            #pragma unroll
            for (int nt = 0; nt < 4; nt++) {
                int c0 = kt * TR + nt * 8 + l4 * 2;
                *(float2*)&sc[rl * SCP + c0] =
                    make_float2(acc[mt][nt][0] * 0.125f, acc[mt][nt][1] * 0.125f);
                *(float2*)&sc[(rl + 8) * SCP + c0] =
                    make_float2(acc[mt][nt][2] * 0.125f, acc[mt][nt][3] * 0.125f);
            }
        }
    }
    __syncthreads();

    // ---- Phase 2: softmax -> cumsum decay -> softmax -> maxout (fp32 exact)
    const float gm = -fabsf(gam[h]);
    #pragma unroll
    for (int rr = 0; rr < 2; rr++) {
        const int r = w + rr * 16;
        const int i = base + r;
        const int nv = i;                          // strict causal: keys j < i
        float* row = sc + r * SCP;
        if (nv == 0) {
            for (int j = lane; j < kLimit; j += 32) row[j] = 0.f;
            continue;
        }
        float mx = -3.4e38f;
        for (int j = lane; j < nv; j += 32) mx = fmaxf(mx, row[j]);
        #pragma unroll
        for (int o = 16; o; o >>= 1) mx = fmaxf(mx, __shfl_xor_sync(~0u, mx, o));
        float sum = 0.f;
        for (int j = lane; j < nv; j += 32) sum += __expf(row[j] - mx);
        #pragma unroll
        for (int o = 16; o; o >>= 1) sum += __shfl_xor_sync(~0u, sum, o);
        const float inv = 1.0f / sum;
        float carry = 0.f;
        for (int c0 = 0; c0 < nv; c0 += 32) {
            int j = c0 + lane;
            bool vld = j < nv;
            float sv = vld ? row[j] : 0.f;
            float p = vld ? __expf(sv - mx) * inv : 0.f;
            #pragma unroll
            for (int o = 1; o < 32; o <<= 1) {
                float t = __shfl_up_sync(~0u, p, o);
                if (lane >= o) p += t;
            }
            float cum = p + carry;
            float nc = __shfl_sync(~0u, cum, 31);
            if (vld) {
                float rem = 1.0f - cum;            // disttotal == 1
                float tt = fmaxf(rem * (float)(i - j), 0.f);
                float eff = fmaxf(__expf(gm * sqrtf(tt)), 1e-5f);
                row[j] = sv * eff;
            }
            carry = nc;
        }
        float mx2 = -3.4e38f;
        for (int j = lane; j < nv; j += 32) mx2 = fmaxf(mx2, row[j]);
        #pragma unroll
        for (int o = 16; o; o >>= 1) mx2 = fmaxf(mx2, __shfl_xor_sync(~0u, mx2, o));
        float sum2 = 0.f;
        for (int j = lane; j < nv; j += 32) sum2 += __expf(row[j] - mx2);
        #pragma unroll
        for (int o = 16; o; o >>= 1) sum2 += __shfl_xor_sync(~0u, sum2, o);
        const float sf = fminf(sum2, 5.0f) / sum2;  // maxout: max(attn)=1/sum2
        for (int j = lane; j < nv; j += 32) row[j] = __expf(row[j] - mx2) * sf;
        for (int j = nv + lane; j < kLimit; j += 32) row[j] = 0.f;
    }
    __syncthreads();

    // ---- Phase 3: out = attn @ V via tf32 mma.
    // Warp w: output cols [(w&7)*8, +8), key tiles of parity (w>>3).
    const int colw = w & 7, half = w >> 3;
    float oacc[2][4] = {};
    for (int kt = half; kt < nkt; kt += 2) {
        const float* vp = vb + (size_t)kt * TR * kDH;
        #pragma unroll
        for (int kk = 0; kk < 4; kk++) {
            uint32_t bf[2];
            const float* p = vp + (size_t)(kk * 8 + l4) * kDH + colw * 8 + gid;
            bf[0] = f2tf(p[0]);
            bf[1] = f2tf(p[4 * kDH]);
            #pragma unroll
            for (int mt = 0; mt < 2; mt++) {
                uint32_t af[4];
                const float* q = sc + (mt * 16 + gid) * SCP + kt * TR + kk * 8 + l4;
                af[0] = f2tf(q[0]);
                af[1] = f2tf(q[8 * SCP]);
                af[2] = f2tf(q[4]);
                af[3] = f2tf(q[8 * SCP + 4]);
                mma8(oacc[mt], af, bf);
            }
        }
    }
    // reduce the two kt-parity halves through smem
    if (half == 1) {
        #pragma unroll
        for (int mt = 0; mt < 2; mt++) {
            int rl = mt * 16 + gid;
            float* rp = red + rl * kDH + colw * 8 + l4 * 2;
            *(float2*)rp = make_float2(oacc[mt][0], oacc[mt][1]);
            *(float2*)(rp + 8 * kDH) = make_float2(oacc[mt][2], oacc[mt][3]);
        }
    }
    __syncthreads();
    if (half == 0) {
        #pragma unroll
        for (int mt = 0; mt < 2; mt++) {
            int rl = mt * 16 + gid;
            const float* rp = red + rl * kDH + colw * 8 + l4 * 2;
            float2 p0 = *(const float2*)rp;
            float2 p1 = *(const float2*)(rp + 8 * kDH);
            int i0 = base + rl;
            float* op = g_ao + ((size_t)b * kS + i0) * kD + h * kDH + colw * 8 + l4 * 2;
            *(float2*)op = make_float2(oacc[mt][0] + p0.x, oacc[mt][1] + p0.y);
            *(float2*)(op + 8 * kD) = make_float2(oacc[mt][2] + p1.x, oacc[mt][3] + p1.y);
        }
    }
}

// ---------------------------------------------------------------------------
template<bool ADD>
__global__ void __launch_bounds__(256) ln_k(const float* __restrict__ X,
                                            const float* __restrict__ Aadd,
                                            const float* __restrict__ g,
                                            const float* __restrict__ bt,
                                            float* __restrict__ out) {
    __shared__ float red[8];
    const int row = blockIdx.x;
    const int tid = threadIdx.x;
    const int lane = tid & 31, w = tid >> 5;
    const float* xr = X + (size_t)row * kD;
    float v[4];
    float s = 0.f;
    #pragma unroll
    for (int t = 0; t < 4; t++) {
        int d = tid + t * 256;
        float val = xr[d];
        if (ADD) val += Aadd[(size_t)row * kD + d];
        v[t] = val;
        s += val;
    }
    #pragma unroll
    for (int o = 16; o; o >>= 1) s += __shfl_xor_sync(~0u, s, o);
    if (lane == 0) red[w] = s;
    __syncthreads();
    float tot = 0.f;
    #pragma unroll
    for (int k = 0; k < 8; k++) tot += red[k];
    const float mu = tot * (1.0f / kD);
    __syncthreads();
    float s2 = 0.f;
    #pragma unroll
    for (int t = 0; t < 4; t++) { float dv = v[t] - mu; s2 += dv * dv; }
    #pragma unroll
    for (int o = 16; o; o >>= 1) s2 += __shfl_xor_sync(~0u, s2, o);
    if (lane == 0) red[w] = s2;
    __syncthreads();
    float tot2 = 0.f;
    #pragma unroll
    for (int k = 0; k < 8; k++) tot2 += red[k];
    const float rs = rsqrtf(tot2 * (1.0f / kD) + 1e-5f);
    #pragma unroll
    for (int t = 0; t < 4; t++) {
        int d = tid + t * 256;
        out[(size_t)row * kD + d] = (v[t] - mu) * rs * g[d] + bt[d];
    }
}

// ---------------------------------------------------------------------------
extern "C" void kernel_launch(void* const* d_in, const int* in_sizes, int n_in,
                              void* d_out, int out_size) {
    (void)in_sizes; (void)n_in; (void)out_size;
    const float* q   = (const float*)d_in[0];
    // d_in[1] = lens (unused in eval mode)
    const float* Wq  = (const float*)d_in[2];
    const float* bq  = (const float*)d_in[3];
    const float* Wv  = (const float*)d_in[4];
    const float* bv  = (const float*)d_in[5];
    const float* Wo  = (const float*)d_in[6];
    const float* bo  = (const float*)d_in[7];
    const float* gm  = (const float*)d_in[8];
    const float* lng = (const float*)d_in[9];
    const float* lnb = (const float*)d_in[10];
    const float* fg  = (const float*)d_in[11];
    const float* fb  = (const float*)d_in[12];
    float* out = (float*)d_out;

    cudaFuncSetAttribute(attn_k, cudaFuncAttributeMaxDynamicSharedMemorySize, ATTN_SMEM);
    cudaFuncSetAttribute(gemm_tf32<true>,  cudaFuncAttributeMaxDynamicSharedMemorySize, GEMM_SMEM);
    cudaFuncSetAttribute(gemm_tf32<false>, cudaFuncAttributeMaxDynamicSharedMemorySize, GEMM_SMEM);

    void* p;
    float *xg, *qhg, *vhg, *aog, *pjg;
    cudaGetSymbolAddress(&p, g_x);    xg  = (float*)p;
    cudaGetSymbolAddress(&p, g_qh);   qhg = (float*)p;
    cudaGetSymbolAddress(&p, g_vh);   vhg = (float*)p;
    cudaGetSymbolAddress(&p, g_ao);   aog = (float*)p;
    cudaGetSymbolAddress(&p, g_proj); pjg = (float*)p;

    copy_k<<<(kBS * kD / 4) / 256, 256>>>(q);

    dim3 ggrid(kD / BN, kBS / BM);   // (8, 16)
    for (int l = 0; l < kL; l++) {
        gemm_tf32<true ><<<ggrid, 256, GEMM_SMEM>>>(xg,  Wq + (size_t)l * kD * kD, bq + l * kD, qhg);
        gemm_tf32<true ><<<ggrid, 256, GEMM_SMEM>>>(xg,  Wv + (size_t)l * kD * kD, bv + l * kD, vhg);
        attn_k<<<kBH * NTILES, ATTN_THREADS, ATTN_SMEM>>>(gm + l * kH);
        gemm_tf32<false><<<ggrid, 256, GEMM_SMEM>>>(aog, Wo + (size_t)l * kD * kD, bo + l * kD, pjg);
        ln_k<true ><<<kBS, 256>>>(xg, pjg, lng + l * kD, lnb + l * kD, xg);
    }
    ln_k<false><<<kBS, 256>>>(xg, nullptr, fg, fb, out);
}

// round 5
// speedup vs baseline: 2.8850x; 1.0469x over previous
#include <cuda_runtime.h>
#include <math.h>
#include <stdint.h>

namespace {
constexpr int kBn = 2, kS = 1024, kD = 1024, kH = 16, kDH = 64, kL = 4;
constexpr int kBS = kBn * kS;          // 2048 rows
constexpr int kBH = kBn * kH;          // 32 (b,h) pairs
constexpr int TR = 16;                 // query rows per attention block
constexpr int NT16 = kS / TR;          // 64 tiles per (b,h)
constexpr int SCP = 1028;              // padded score-row stride (stride%32==4)
constexpr int ATTN_THREADS = 256;      // 8 warps
constexpr int ATTN_SMEM = TR * SCP * 4;  // 65792 B -> 2 CTAs/SM
// GEMM tiling
constexpr int BM = 128, BN = 128, BK = 32;
constexpr int ASTR = 36, BSTR = 136;   // padded smem strides
constexpr int GEMM_SMEM = (2 * BM * ASTR + 2 * BK * BSTR) * 4;  // 71680 B
}

// Scratch (static device allocations; no runtime allocs)
__device__ float g_x[kBS * kD];
__device__ float g_qh[kBH * kS * kDH];
__device__ float g_vh[kBH * kS * kDH];
__device__ float g_ao[kBS * kD];
__device__ float g_proj[kBS * kD];

// ---------------------------------------------------------------------------
__device__ __forceinline__ uint32_t f2tf(float x) {
    uint32_t r;
    asm("cvt.rna.tf32.f32 %0, %1;" : "=r"(r) : "f"(x));
    return r;
}
__device__ __forceinline__ void mma8(float* d, const uint32_t* a, const uint32_t* b) {
    asm volatile(
        "mma.sync.aligned.m16n8k8.row.col.f32.tf32.tf32.f32 "
        "{%0,%1,%2,%3}, {%4,%5,%6,%7}, {%8,%9}, {%0,%1,%2,%3};\n"
        : "+f"(d[0]), "+f"(d[1]), "+f"(d[2]), "+f"(d[3])
        : "r"(a[0]), "r"(a[1]), "r"(a[2]), "r"(a[3]), "r"(b[0]), "r"(b[1]));
}

// ---------------------------------------------------------------------------
__global__ void copy_k(const float* __restrict__ in) {
    int i = blockIdx.x * blockDim.x + threadIdx.x;
    reinterpret_cast<float4*>(g_x)[i] = reinterpret_cast<const float4*>(in)[i];
}

// ---------------------------------------------------------------------------
// C[2048,1024] = A @ W + bias, tf32 tensor cores, cp.async double buffering.
// Block 128x128, 8 warps of 32x64. SCATTER writes (B,H,S,DH) layout.
template<bool SCATTER>
__global__ void __launch_bounds__(256) gemm_tf32(const float* __restrict__ A,
                                                 const float* __restrict__ W,
                                                 const float* __restrict__ bias,
                                                 float* __restrict__ C) {
    extern __shared__ float sm[];
    float* As = sm;
    float* Bs = sm + 2 * BM * ASTR;
    const int tid = threadIdx.x, lane = tid & 31, w = tid >> 5;
    const int gid = lane >> 2, l4 = lane & 3;
    const int warpM = w & 3, warpN = w >> 2;
    const int mbase = blockIdx.y * BM, nbase = blockIdx.x * BN;
    const uint32_t sA = (uint32_t)__cvta_generic_to_shared(As);
    const uint32_t sB = (uint32_t)__cvta_generic_to_shared(Bs);

    auto prefetch = [&](int kt, int buf) {
        #pragma unroll
        for (int i = 0; i < 4; i++) {
            int cid = tid + i * 256;
            int m = cid >> 3, kc = cid & 7;
            uint32_t dst = sA + (uint32_t)((buf * BM * ASTR + m * ASTR + kc * 4) * 4);
            const float* src = A + (size_t)(mbase + m) * kD + kt * BK + kc * 4;
            asm volatile("cp.async.cg.shared.global [%0], [%1], 16;\n" ::"r"(dst), "l"(src));
        }
        #pragma unroll
        for (int i = 0; i < 4; i++) {
            int cid = tid + i * 256;
            int k = cid >> 5, nc = cid & 31;   // full 32 x 128 tile
            uint32_t dst = sB + (uint32_t)((buf * BK * BSTR + k * BSTR + nc * 4) * 4);
            const float* src = W + (size_t)(kt * BK + k) * kD + nbase + nc * 4;
            asm volatile("cp.async.cg.shared.global [%0], [%1], 16;\n" ::"r"(dst), "l"(src));
        }
        asm volatile("cp.async.commit_group;\n");
    };

    float acc[2][8][4] = {};
    prefetch(0, 0);
    const int nK = kD / BK;
    for (int kt = 0; kt < nK; kt++) {
        asm volatile("cp.async.wait_group 0;\n");
        __syncthreads();
        if (kt + 1 < nK) prefetch(kt + 1, (kt + 1) & 1);
        const float* as = As + (kt & 1) * BM * ASTR;
        const float* bs = Bs + (kt & 1) * BK * BSTR;
        #pragma unroll
        for (int ks = 0; ks < 4; ks++) {
            uint32_t af[2][4];
            #pragma unroll
            for (int mt = 0; mt < 2; mt++) {
                int r = warpM * 32 + mt * 16 + gid;
                const float* p = as + r * ASTR + ks * 8 + l4;
                af[mt][0] = f2tf(p[0]);
                af[mt][1] = f2tf(p[8 * ASTR]);
                af[mt][2] = f2tf(p[4]);
                af[mt][3] = f2tf(p[8 * ASTR + 4]);
            }
            #pragma unroll
            for (int nt = 0; nt < 8; nt++) {
                uint32_t bf[2];
                int cn = warpN * 64 + nt * 8 + gid;
                const float* p = bs + (ks * 8 + l4) * BSTR + cn;
                bf[0] = f2tf(p[0]);
                bf[1] = f2tf(p[4 * BSTR]);
                #pragma unroll
                for (int mt = 0; mt < 2; mt++) mma8(acc[mt][nt], af[mt], bf);
            }
        }
        __syncthreads();
    }
    #pragma unroll
    for (int mt = 0; mt < 2; mt++) {
        int r0 = mbase + warpM * 32 + mt * 16 + gid;
        #pragma unroll
        for (int nt = 0; nt < 8; nt++) {
            int cc = nbase + warpN * 64 + nt * 8 + l4 * 2;
            float b0 = bias[cc], b1 = bias[cc + 1];
            float2 u = make_float2(acc[mt][nt][0] + b0, acc[mt][nt][1] + b1);
            float2 v = make_float2(acc[mt][nt][2] + b0, acc[mt][nt][3] + b1);
            if (SCATTER) {
                int bb = r0 / kS, s = r0 - bb * kS;
                int h = cc >> 6, d = cc & 63;
                *(float2*)&C[(((size_t)bb * kH + h) * kS + s) * kDH + d] = u;
                *(float2*)&C[(((size_t)bb * kH + h) * kS + s + 8) * kDH + d] = v;
            } else {
                *(float2*)&C[(size_t)r0 * kD + cc] = u;
                *(float2*)&C[(size_t)(r0 + 8) * kD + cc] = v;
            }
        }
    }
}

// ---------------------------------------------------------------------------
// Gamma attention, 16 query rows per block, 8 warps, 2 CTAs/SM.
// bh = bx & 31, tile = 63 - (bx >> 5)  => longest blocks scheduled first.
__global__ void __launch_bounds__(ATTN_THREADS, 2) attn_k(const float* __restrict__ gam) {
    extern __shared__ float sc[];                 // [TR][SCP] score rows

    const int bx = blockIdx.x;
    const int bh = bx & (kBH - 1);
    const int tile = (NT16 - 1) - (bx >> 5);
    const int h = bh & (kH - 1);
    const int b = bh >> 4;
    const int base = tile * TR;
    const int tid = threadIdx.x, lane = tid & 31, w = tid >> 5;
    const int gid = lane >> 2, l4 = lane & 3;
    const float* qb = g_qh + (size_t)bh * kS * kDH;
    const float* vb = g_vh + (size_t)bh * kS * kDH;
    const int nkt = tile + 1, kLimit = nkt * TR;

    // ---- Phase 1: scores = QK^T / 8. Hoist Q fragments (cvt once).
    {
        uint32_t qa[8][4];
        #pragma unroll
        for (int ks = 0; ks < 8; ks++) {
            const float* p = qb + (size_t)(base + gid) * kDH + ks * 8 + l4;
            qa[ks][0] = f2tf(p[0]);
            qa[ks][1] = f2tf(p[8 * kDH]);
            qa[ks][2] = f2tf(p[4]);
            qa[ks][3] = f2tf(p[8 * kDH + 4]);
        }
        for (int kt = w; kt < nkt; kt += 8) {
            const float* kp = qb + (size_t)kt * TR * kDH;
            float acc[2][4] = {};
            #pragma unroll
            for (int ks = 0; ks < 8; ks++) {
                #pragma unroll
                for (int nt = 0; nt < 2; nt++) {
                    uint32_t bf[2];
                    const float* p = kp + (size_t)(nt * 8 + gid) * kDH + ks * 8 + l4;
                    bf[0] = f2tf(p[0]);
                    bf[1] = f2tf(p[4]);
                    mma8(acc[nt], qa[ks], bf);
                }
            }
            #pragma unroll
            for (int nt = 0; nt < 2; nt++) {
                int c0 = kt * TR + nt * 8 + l4 * 2;
                *(float2*)&sc[gid * SCP + c0] =
                    make_float2(acc[nt][0] * 0.125f, acc[nt][1] * 0.125f);
                *(float2*)&sc[(gid + 8) * SCP + c0] =
                    make_float2(acc[nt][2] * 0.125f, acc[nt][3] * 0.125f);
            }
        }
    }
    __syncthreads();

    // ---- Phase 2: softmax -> cumsum decay -> softmax -> maxout (fp32 exact)
    const float gm = -fabsf(gam[h]);
    #pragma unroll
    for (int rr = 0; rr < 2; rr++) {
        const int r = w + rr * 8;
        const int i = base + r;
        const int nv = i;                          // strict causal: keys j < i
        float* row = sc + r * SCP;
        if (nv == 0) {
            for (int j = lane; j < kLimit; j += 32) row[j] = 0.f;
            continue;
        }
        float mx = -3.4e38f;
        for (int j = lane; j < nv; j += 32) mx = fmaxf(mx, row[j]);
        #pragma unroll
        for (int o = 16; o; o >>= 1) mx = fmaxf(mx, __shfl_xor_sync(~0u, mx, o));
        float sum = 0.f;
        for (int j = lane; j < nv; j += 32) sum += __expf(row[j] - mx);
        #pragma unroll
        for (int o = 16; o; o >>= 1) sum += __shfl_xor_sync(~0u, sum, o);
        const float inv = 1.0f / sum;
        float carry = 0.f;
        for (int c0 = 0; c0 < nv; c0 += 32) {
            int j = c0 + lane;
            bool vld = j < nv;
            float sv = vld ? row[j] : 0.f;
            float p = vld ? __expf(sv - mx) * inv : 0.f;
            #pragma unroll
            for (int o = 1; o < 32; o <<= 1) {
                float t = __shfl_up_sync(~0u, p, o);
                if (lane >= o) p += t;
            }
            float cum = p + carry;
            float nc = __shfl_sync(~0u, cum, 31);
            if (vld) {
                float rem = 1.0f - cum;            // disttotal == 1
                float tt = fmaxf(rem * (float)(i - j), 0.f);
                float eff = fmaxf(__expf(gm * sqrtf(tt)), 1e-5f);
                row[j] = sv * eff;
            }
            carry = nc;
        }
        float mx2 = -3.4e38f;
        for (int j = lane; j < nv; j += 32) mx2 = fmaxf(mx2, row[j]);
        #pragma unroll
        for (int o = 16; o; o >>= 1) mx2 = fmaxf(mx2, __shfl_xor_sync(~0u, mx2, o));
        float sum2 = 0.f;
        for (int j = lane; j < nv; j += 32) sum2 += __expf(row[j] - mx2);
        #pragma unroll
        for (int o = 16; o; o >>= 1) sum2 += __shfl_xor_sync(~0u, sum2, o);
        const float sf = fminf(sum2, 5.0f) / sum2;  // maxout: max(attn)=1/sum2
        for (int j = lane; j < nv; j += 32) row[j] = __expf(row[j] - mx2) * sf;
        for (int j = nv + lane; j < kLimit; j += 32) row[j] = 0.f;
    }
    __syncthreads();

    // ---- Phase 3: out = attn @ V. Warp w owns output cols [w*8, w*8+8).
    float oacc[4] = {};
    for (int kt = 0; kt < nkt; kt++) {
        const float* vp = vb + (size_t)kt * TR * kDH;
        #pragma unroll
        for (int kk = 0; kk < 2; kk++) {
            uint32_t bf[2];
            const float* p = vp + (size_t)(kk * 8 + l4) * kDH + w * 8 + gid;
            bf[0] = f2tf(p[0]);
            bf[1] = f2tf(p[4 * kDH]);
            uint32_t af[4];
            const float* q = sc + gid * SCP + kt * TR + kk * 8 + l4;
            af[0] = f2tf(q[0]);
            af[1] = f2tf(q[8 * SCP]);
            af[2] = f2tf(q[4]);
            af[3] = f2tf(q[8 * SCP + 4]);
            mma8(oacc, af, bf);
        }
    }
    {
        const int i0 = base + gid;
        float* op = g_ao + ((size_t)b * kS + i0) * kD + h * kDH + w * 8 + l4 * 2;
        *(float2*)op = make_float2(oacc[0], oacc[1]);
        *(float2*)(op + 8 * kD) = make_float2(oacc[2], oacc[3]);
    }
}

// ---------------------------------------------------------------------------
template<bool ADD>
__global__ void __launch_bounds__(256) ln_k(const float* __restrict__ X,
                                            const float* __restrict__ Aadd,
                                            const float* __restrict__ g,
                                            const float* __restrict__ bt,
                                            float* __restrict__ out) {
    __shared__ float red[8];
    const int row = blockIdx.x;
    const int tid = threadIdx.x;
    const int lane = tid & 31, w = tid >> 5;
    const float* xr = X + (size_t)row * kD;
    float v[4];
    float s = 0.f;
    #pragma unroll
    for (int t = 0; t < 4; t++) {
        int d = tid + t * 256;
        float val = xr[d];
        if (ADD) val += Aadd[(size_t)row * kD + d];
        v[t] = val;
        s += val;
    }
    #pragma unroll
    for (int o = 16; o; o >>= 1) s += __shfl_xor_sync(~0u, s, o);
    if (lane == 0) red[w] = s;
    __syncthreads();
    float tot = 0.f;
    #pragma unroll
    for (int k = 0; k < 8; k++) tot += red[k];
    const float mu = tot * (1.0f / kD);
    __syncthreads();
    float s2 = 0.f;
    #pragma unroll
    for (int t = 0; t < 4; t++) { float dv = v[t] - mu; s2 += dv * dv; }
    #pragma unroll
    for (int o = 16; o; o >>= 1) s2 += __shfl_xor_sync(~0u, s2, o);
    if (lane == 0) red[w] = s2;
    __syncthreads();
    float tot2 = 0.f;
    #pragma unroll
    for (int k = 0; k < 8; k++) tot2 += red[k];
    const float rs = rsqrtf(tot2 * (1.0f / kD) + 1e-5f);
    #pragma unroll
    for (int t = 0; t < 4; t++) {
        int d = tid + t * 256;
        out[(size_t)row * kD + d] = (v[t] - mu) * rs * g[d] + bt[d];
    }
}

// ---------------------------------------------------------------------------
extern "C" void kernel_launch(void* const* d_in, const int* in_sizes, int n_in,
                              void* d_out, int out_size) {
    (void)in_sizes; (void)n_in; (void)out_size;
    const float* q   = (const float*)d_in[0];
    // d_in[1] = lens (unused in eval mode)
    const float* Wq  = (const float*)d_in[2];
    const float* bq  = (const float*)d_in[3];
    const float* Wv  = (const float*)d_in[4];
    const float* bv  = (const float*)d_in[5];
    const float* Wo  = (const float*)d_in[6];
    const float* bo  = (const float*)d_in[7];
    const float* gm  = (const float*)d_in[8];
    const float* lng = (const float*)d_in[9];
    const float* lnb = (const float*)d_in[10];
    const float* fg  = (const float*)d_in[11];
    const float* fb  = (const float*)d_in[12];
    float* out = (float*)d_out;

    cudaFuncSetAttribute(attn_k, cudaFuncAttributeMaxDynamicSharedMemorySize, ATTN_SMEM);
    cudaFuncSetAttribute(gemm_tf32<true>,  cudaFuncAttributeMaxDynamicSharedMemorySize, GEMM_SMEM);
    cudaFuncSetAttribute(gemm_tf32<false>, cudaFuncAttributeMaxDynamicSharedMemorySize, GEMM_SMEM);

    void* p;
    float *xg, *qhg, *vhg, *aog, *pjg;
    cudaGetSymbolAddress(&p, g_x);    xg  = (float*)p;
    cudaGetSymbolAddress(&p, g_qh);   qhg = (float*)p;
    cudaGetSymbolAddress(&p, g_vh);   vhg = (float*)p;
    cudaGetSymbolAddress(&p, g_ao);   aog = (float*)p;
    cudaGetSymbolAddress(&p, g_proj); pjg = (float*)p;

    copy_k<<<(kBS * kD / 4) / 256, 256>>>(q);

    dim3 ggrid(kD / BN, kBS / BM);   // (8, 16)
    for (int l = 0; l < kL; l++) {
        gemm_tf32<true ><<<ggrid, 256, GEMM_SMEM>>>(xg,  Wq + (size_t)l * kD * kD, bq + l * kD, qhg);
        gemm_tf32<true ><<<ggrid, 256, GEMM_SMEM>>>(xg,  Wv + (size_t)l * kD * kD, bv + l * kD, vhg);
        attn_k<<<kBH * NT16, ATTN_THREADS, ATTN_SMEM>>>(gm + l * kH);
        gemm_tf32<false><<<ggrid, 256, GEMM_SMEM>>>(aog, Wo + (size_t)l * kD * kD, bo + l * kD, pjg);
        ln_k<true ><<<kBS, 256>>>(xg, pjg, lng + l * kD, lnb + l * kD, xg);
    }
    ln_k<false><<<kBS, 256>>>(xg, nullptr, fg, fb, out);
}

// round 6
// speedup vs baseline: 2.9542x; 1.0240x over previous
#include <cuda_runtime.h>
#include <math.h>
#include <stdint.h>

namespace {
constexpr int kBn = 2, kS = 1024, kD = 1024, kH = 16, kDH = 64, kL = 4;
constexpr int kBS = kBn * kS;          // 2048 rows
constexpr int kBH = kBn * kH;          // 32 (b,h) pairs
constexpr int TR = 16;                 // query rows per attention block
constexpr int NT16 = kS / TR;          // 64 tiles per (b,h)
constexpr int SCP = 1028;              // padded score-row stride (stride%32==4)
constexpr int ATTN_THREADS = 256;      // 8 warps
constexpr int ATTN_SMEM = TR * SCP * 4;  // 65792 B -> 3 CTAs/SM
// GEMM tiling
constexpr int BM = 128, BN = 128, BK = 32;
constexpr int ASTR = 36, BSTR = 136;   // padded smem strides
constexpr int GEMM_SMEM = (2 * BM * ASTR + 2 * BK * BSTR) * 4;  // 71680 B
}

// Scratch (static device allocations; no runtime allocs)
__device__ float g_x[kBS * kD];
__device__ float g_qh[kBH * kS * kDH];
__device__ float g_vh[kBH * kS * kDH];
__device__ float g_ao[kBS * kD];
__device__ float g_proj[kBS * kD];

// ---------------------------------------------------------------------------
__device__ __forceinline__ uint32_t f2tf(float x) {
    uint32_t r;
    asm("cvt.rna.tf32.f32 %0, %1;" : "=r"(r) : "f"(x));
    return r;
}
__device__ __forceinline__ float sqrt_approx(float x) {
    float r;
    asm("sqrt.approx.f32 %0, %1;" : "=f"(r) : "f"(x));
    return r;
}
__device__ __forceinline__ void mma8(float* d, const uint32_t* a, const uint32_t* b) {
    asm volatile(
        "mma.sync.aligned.m16n8k8.row.col.f32.tf32.tf32.f32 "
        "{%0,%1,%2,%3}, {%4,%5,%6,%7}, {%8,%9}, {%0,%1,%2,%3};\n"
        : "+f"(d[0]), "+f"(d[1]), "+f"(d[2]), "+f"(d[3])
        : "r"(a[0]), "r"(a[1]), "r"(a[2]), "r"(a[3]), "r"(b[0]), "r"(b[1]));
}

// ---------------------------------------------------------------------------
__global__ void copy_k(const float* __restrict__ in) {
    int i = blockIdx.x * blockDim.x + threadIdx.x;
    reinterpret_cast<float4*>(g_x)[i] = reinterpret_cast<const float4*>(in)[i];
}

// ---------------------------------------------------------------------------
// C[2048,1024] = A @ W + bias, tf32 tensor cores, cp.async double buffering.
// Block 128x128, 8 warps of 32x64. SCATTER writes (B,H,S,DH) layout.
template<bool SCATTER>
__global__ void __launch_bounds__(256) gemm_tf32(const float* __restrict__ A,
                                                 const float* __restrict__ W,
                                                 const float* __restrict__ bias,
                                                 float* __restrict__ C) {
    extern __shared__ float sm[];
    float* As = sm;
    float* Bs = sm + 2 * BM * ASTR;
    const int tid = threadIdx.x, lane = tid & 31, w = tid >> 5;
    const int gid = lane >> 2, l4 = lane & 3;
    const int warpM = w & 3, warpN = w >> 2;
    const int mbase = blockIdx.y * BM, nbase = blockIdx.x * BN;
    const uint32_t sA = (uint32_t)__cvta_generic_to_shared(As);
    const uint32_t sB = (uint32_t)__cvta_generic_to_shared(Bs);

    auto prefetch = [&](int kt, int buf) {
        #pragma unroll
        for (int i = 0; i < 4; i++) {
            int cid = tid + i * 256;
            int m = cid >> 3, kc = cid & 7;
            uint32_t dst = sA + (uint32_t)((buf * BM * ASTR + m * ASTR + kc * 4) * 4);
            const float* src = A + (size_t)(mbase + m) * kD + kt * BK + kc * 4;
            asm volatile("cp.async.cg.shared.global [%0], [%1], 16;\n" ::"r"(dst), "l"(src));
        }
        #pragma unroll
        for (int i = 0; i < 4; i++) {
            int cid = tid + i * 256;
            int k = cid >> 5, nc = cid & 31;   // full 32 x 128 tile
            uint32_t dst = sB + (uint32_t)((buf * BK * BSTR + k * BSTR + nc * 4) * 4);
            const float* src = W + (size_t)(kt * BK + k) * kD + nbase + nc * 4;
            asm volatile("cp.async.cg.shared.global [%0], [%1], 16;\n" ::"r"(dst), "l"(src));
        }
        asm volatile("cp.async.commit_group;\n");
    };

    float acc[2][8][4] = {};
    prefetch(0, 0);
    const int nK = kD / BK;
    for (int kt = 0; kt < nK; kt++) {
        asm volatile("cp.async.wait_group 0;\n");
        __syncthreads();
        if (kt + 1 < nK) prefetch(kt + 1, (kt + 1) & 1);
        const float* as = As + (kt & 1) * BM * ASTR;
        const float* bs = Bs + (kt & 1) * BK * BSTR;
        #pragma unroll
        for (int ks = 0; ks < 4; ks++) {
            uint32_t af[2][4];
            #pragma unroll
            for (int mt = 0; mt < 2; mt++) {
                int r = warpM * 32 + mt * 16 + gid;
                const float* p = as + r * ASTR + ks * 8 + l4;
                af[mt][0] = f2tf(p[0]);
                af[mt][1] = f2tf(p[8 * ASTR]);
                af[mt][2] = f2tf(p[4]);
                af[mt][3] = f2tf(p[8 * ASTR + 4]);
            }
            #pragma unroll
            for (int nt = 0; nt < 8; nt++) {
                uint32_t bf[2];
                int cn = warpN * 64 + nt * 8 + gid;
                const float* p = bs + (ks * 8 + l4) * BSTR + cn;
                bf[0] = f2tf(p[0]);
                bf[1] = f2tf(p[4 * BSTR]);
                #pragma unroll
                for (int mt = 0; mt < 2; mt++) mma8(acc[mt][nt], af[mt], bf);
            }
        }
        __syncthreads();
    }
    #pragma unroll
    for (int mt = 0; mt < 2; mt++) {
        int r0 = mbase + warpM * 32 + mt * 16 + gid;
        #pragma unroll
        for (int nt = 0; nt < 8; nt++) {
            int cc = nbase + warpN * 64 + nt * 8 + l4 * 2;
            float b0 = bias[cc], b1 = bias[cc + 1];
            float2 u = make_float2(acc[mt][nt][0] + b0, acc[mt][nt][1] + b1);
            float2 v = make_float2(acc[mt][nt][2] + b0, acc[mt][nt][3] + b1);
            if (SCATTER) {
                int bb = r0 / kS, s = r0 - bb * kS;
                int h = cc >> 6, d = cc & 63;
                *(float2*)&C[(((size_t)bb * kH + h) * kS + s) * kDH + d] = u;
                *(float2*)&C[(((size_t)bb * kH + h) * kS + s + 8) * kDH + d] = v;
            } else {
                *(float2*)&C[(size_t)r0 * kD + cc] = u;
                *(float2*)&C[(size_t)(r0 + 8) * kD + cc] = v;
            }
        }
    }
}

// ---------------------------------------------------------------------------
// Gamma attention, 16 query rows per block, 8 warps, 3 CTAs/SM.
// bh = bx & 31, tile = 63 - (bx >> 5)  => longest blocks scheduled first.
__global__ void __launch_bounds__(ATTN_THREADS, 3) attn_k(const float* __restrict__ gam) {
    extern __shared__ float sc[];                 // [TR][SCP] score rows

    const int bx = blockIdx.x;
    const int bh = bx & (kBH - 1);
    const int tile = (NT16 - 1) - (bx >> 5);
    const int h = bh & (kH - 1);
    const int b = bh >> 4;
    const int base = tile * TR;
    const int tid = threadIdx.x, lane = tid & 31, w = tid >> 5;
    const int gid = lane >> 2, l4 = lane & 3;
    const float* qb = g_qh + (size_t)bh * kS * kDH;
    const float* vb = g_vh + (size_t)bh * kS * kDH;
    const int nkt = tile + 1, kLimit = nkt * TR;

    // ---- Phase 1: scores = QK^T / 8. Hoist Q fragments (cvt once).
    {
        uint32_t qa[8][4];
        #pragma unroll
        for (int ks = 0; ks < 8; ks++) {
            const float* p = qb + (size_t)(base + gid) * kDH + ks * 8 + l4;
            qa[ks][0] = f2tf(p[0]);
            qa[ks][1] = f2tf(p[8 * kDH]);
            qa[ks][2] = f2tf(p[4]);
            qa[ks][3] = f2tf(p[8 * kDH + 4]);
        }
        for (int kt = w; kt < nkt; kt += 8) {
            const float* kp = qb + (size_t)kt * TR * kDH;
            float acc[2][4] = {};
            #pragma unroll
            for (int ks = 0; ks < 8; ks++) {
                #pragma unroll
                for (int nt = 0; nt < 2; nt++) {
                    uint32_t bf[2];
                    const float* p = kp + (size_t)(nt * 8 + gid) * kDH + ks * 8 + l4;
                    bf[0] = f2tf(p[0]);
                    bf[1] = f2tf(p[4]);
                    mma8(acc[nt], qa[ks], bf);
                }
            }
            #pragma unroll
            for (int nt = 0; nt < 2; nt++) {
                int c0 = kt * TR + nt * 8 + l4 * 2;
                *(float2*)&sc[gid * SCP + c0] =
                    make_float2(acc[nt][0] * 0.125f, acc[nt][1] * 0.125f);
                *(float2*)&sc[(gid + 8) * SCP + c0] =
                    make_float2(acc[nt][2] * 0.125f, acc[nt][3] * 0.125f);
            }
        }
    }
    __syncthreads();

    // ---- Phase 2: fused online softmax -> scan decay -> online softmax ->
    // maxout. 3 row passes. Warp w handles rows w and w+8 interleaved.
    {
        const float gm = -fabsf(gam[h]);
        const int i0r = base + w;
        const int i1r = i0r + 8;
        float* row0 = sc + w * SCP;
        float* row1 = sc + (w + 8) * SCP;
        const int nv0 = i0r, nv1 = i1r;   // strict causal: keys j < i

        // Pass A: lane-private online max/sum, then merged shuffle reduce.
        float m0 = -3.4e38f, s0 = 0.f, m1 = -3.4e38f, s1 = 0.f;
        for (int j = lane; j < nv1; j += 32) {
            if (j < nv0) {
                float v = row0[j];
                if (v > m0) { s0 = s0 * __expf(m0 - v) + 1.f; m0 = v; }
                else        s0 += __expf(v - m0);
            }
            float v1 = row1[j];
            if (v1 > m1) { s1 = s1 * __expf(m1 - v1) + 1.f; m1 = v1; }
            else         s1 += __expf(v1 - m1);
        }
        #pragma unroll
        for (int o = 16; o; o >>= 1) {
            float om = __shfl_xor_sync(~0u, m0, o);
            float os = __shfl_xor_sync(~0u, s0, o);
            float nm = fmaxf(m0, om);
            s0 = s0 * __expf(m0 - nm) + os * __expf(om - nm);
            m0 = nm;
            om = __shfl_xor_sync(~0u, m1, o);
            os = __shfl_xor_sync(~0u, s1, o);
            nm = fmaxf(m1, om);
            s1 = s1 * __expf(m1 - nm) + os * __expf(om - nm);
            m1 = nm;
        }
        const float inv0 = (nv0 > 0) ? 1.f / s0 : 0.f;
        const float inv1 = 1.f / s1;

        // Pass B: warp-scan cumsum of p, apply decay, store s2, online stats2.
        float carry0 = 0.f, carry1 = 0.f;
        float n0 = -3.4e38f, t0 = 0.f, n1 = -3.4e38f, t1 = 0.f;
        for (int c0 = 0; c0 < nv1; c0 += 32) {
            int j = c0 + lane;
            if (c0 < nv0) {
                bool vld = j < nv0;
                float sv = vld ? row0[j] : 0.f;
                float p = vld ? __expf(sv - m0) * inv0 : 0.f;
                #pragma unroll
                for (int o = 1; o < 32; o <<= 1) {
                    float t = __shfl_up_sync(~0u, p, o);
                    if (lane >= o) p += t;
                }
                float cum = p + carry0;
                carry0 = __shfl_sync(~0u, cum, 31);
                if (vld) {
                    float rem = 1.0f - cum;              // disttotal == 1
                    float tt = fmaxf(rem * (float)(i0r - j), 0.f);
                    float eff = fmaxf(__expf(gm * sqrt_approx(tt)), 1e-5f);
                    float s2 = sv * eff;
                    row0[j] = s2;
                    if (s2 > n0) { t0 = t0 * __expf(n0 - s2) + 1.f; n0 = s2; }
                    else         t0 += __expf(s2 - n0);
                }
            }
            {
                bool vld = j < nv1;
                float sv = vld ? row1[j] : 0.f;
                float p = vld ? __expf(sv - m1) * inv1 : 0.f;
                #pragma unroll
                for (int o = 1; o < 32; o <<= 1) {
                    float t = __shfl_up_sync(~0u, p, o);
                    if (lane >= o) p += t;
                }
                float cum = p + carry1;
                carry1 = __shfl_sync(~0u, cum, 31);
                if (vld) {
                    float rem = 1.0f - cum;
                    float tt = fmaxf(rem * (float)(i1r - j), 0.f);
                    float eff = fmaxf(__expf(gm * sqrt_approx(tt)), 1e-5f);
                    float s2 = sv * eff;
                    row1[j] = s2;
                    if (s2 > n1) { t1 = t1 * __expf(n1 - s2) + 1.f; n1 = s2; }
                    else         t1 += __expf(s2 - n1);
                }
            }
        }
        #pragma unroll
        for (int o = 16; o; o >>= 1) {
            float om = __shfl_xor_sync(~0u, n0, o);
            float os = __shfl_xor_sync(~0u, t0, o);
            float nm = fmaxf(n0, om);
            t0 = t0 * __expf(n0 - nm) + os * __expf(om - nm);
            n0 = nm;
            om = __shfl_xor_sync(~0u, n1, o);
            os = __shfl_xor_sync(~0u, t1, o);
            nm = fmaxf(n1, om);
            t1 = t1 * __expf(n1 - nm) + os * __expf(om - nm);
            n1 = nm;
        }
        // maxout: max(attn) = 1/sum2 exactly => scale = min(sum2,5)/sum2
        const float sf0 = (nv0 > 0) ? fminf(t0, 5.f) / t0 : 0.f;
        const float sf1 = fminf(t1, 5.f) / t1;

        // Pass C: finalize attn values, zero-fill the causal tail.
        for (int j = lane; j < kLimit; j += 32) {
            float o0 = (j < nv0) ? __expf(row0[j] - n0) * sf0 : 0.f;
            float o1 = (j < nv1) ? __expf(row1[j] - n1) * sf1 : 0.f;
            row0[j] = o0;
            row1[j] = o1;
        }
    }
    __syncthreads();

    // ---- Phase 3: out = attn @ V. Warp w owns output cols [w*8, w*8+8).
    float oacc[4] = {};
    for (int kt = 0; kt < nkt; kt++) {
        const float* vp = vb + (size_t)kt * TR * kDH;
        #pragma unroll
        for (int kk = 0; kk < 2; kk++) {
            uint32_t bf[2];
            const float* p = vp + (size_t)(kk * 8 + l4) * kDH + w * 8 + gid;
            bf[0] = f2tf(p[0]);
            bf[1] = f2tf(p[4 * kDH]);
            uint32_t af[4];
            const float* q = sc + gid * SCP + kt * TR + kk * 8 + l4;
            af[0] = f2tf(q[0]);
            af[1] = f2tf(q[8 * SCP]);
            af[2] = f2tf(q[4]);
            af[3] = f2tf(q[8 * SCP + 4]);
            mma8(oacc, af, bf);
        }
    }
    {
        const int i0 = base + gid;
        float* op = g_ao + ((size_t)b * kS + i0) * kD + h * kDH + w * 8 + l4 * 2;
        *(float2*)op = make_float2(oacc[0], oacc[1]);
        *(float2*)(op + 8 * kD) = make_float2(oacc[2], oacc[3]);
    }
}

// ---------------------------------------------------------------------------
template<bool ADD>
__global__ void __launch_bounds__(256) ln_k(const float* __restrict__ X,
                                            const float* __restrict__ Aadd,
                                            const float* __restrict__ g,
                                            const float* __restrict__ bt,
                                            float* __restrict__ out) {
    __shared__ float red[8];
    const int row = blockIdx.x;
    const int tid = threadIdx.x;
    const int lane = tid & 31, w = tid >> 5;
    const float* xr = X + (size_t)row * kD;
    float v[4];
    float s = 0.f;
    #pragma unroll
    for (int t = 0; t < 4; t++) {
        int d = tid + t * 256;
        float val = xr[d];
        if (ADD) val += Aadd[(size_t)row * kD + d];
        v[t] = val;
        s += val;
    }
    #pragma unroll
    for (int o = 16; o; o >>= 1) s += __shfl_xor_sync(~0u, s, o);
    if (lane == 0) red[w] = s;
    __syncthreads();
    float tot = 0.f;
    #pragma unroll
    for (int k = 0; k < 8; k++) tot += red[k];
    const float mu = tot * (1.0f / kD);
    __syncthreads();
    float s2 = 0.f;
    #pragma unroll
    for (int t = 0; t < 4; t++) { float dv = v[t] - mu; s2 += dv * dv; }
    #pragma unroll
    for (int o = 16; o; o >>= 1) s2 += __shfl_xor_sync(~0u, s2, o);
    if (lane == 0) red[w] = s2;
    __syncthreads();
    float tot2 = 0.f;
    #pragma unroll
    for (int k = 0; k < 8; k++) tot2 += red[k];
    const float rs = rsqrtf(tot2 * (1.0f / kD) + 1e-5f);
    #pragma unroll
    for (int t = 0; t < 4; t++) {
        int d = tid + t * 256;
        out[(size_t)row * kD + d] = (v[t] - mu) * rs * g[d] + bt[d];
    }
}

// ---------------------------------------------------------------------------
extern "C" void kernel_launch(void* const* d_in, const int* in_sizes, int n_in,
                              void* d_out, int out_size) {
    (void)in_sizes; (void)n_in; (void)out_size;
    const float* q   = (const float*)d_in[0];
    // d_in[1] = lens (unused in eval mode)
    const float* Wq  = (const float*)d_in[2];
    const float* bq  = (const float*)d_in[3];
    const float* Wv  = (const float*)d_in[4];
    const float* bv  = (const float*)d_in[5];
    const float* Wo  = (const float*)d_in[6];
    const float* bo  = (const float*)d_in[7];
    const float* gm  = (const float*)d_in[8];
    const float* lng = (const float*)d_in[9];
    const float* lnb = (const float*)d_in[10];
    const float* fg  = (const float*)d_in[11];
    const float* fb  = (const float*)d_in[12];
    float* out = (float*)d_out;

    cudaFuncSetAttribute(attn_k, cudaFuncAttributeMaxDynamicSharedMemorySize, ATTN_SMEM);
    cudaFuncSetAttribute(gemm_tf32<true>,  cudaFuncAttributeMaxDynamicSharedMemorySize, GEMM_SMEM);
    cudaFuncSetAttribute(gemm_tf32<false>, cudaFuncAttributeMaxDynamicSharedMemorySize, GEMM_SMEM);

    void* p;
    float *xg, *qhg, *vhg, *aog, *pjg;
    cudaGetSymbolAddress(&p, g_x);    xg  = (float*)p;
    cudaGetSymbolAddress(&p, g_qh);   qhg = (float*)p;
    cudaGetSymbolAddress(&p, g_vh);   vhg = (float*)p;
    cudaGetSymbolAddress(&p, g_ao);   aog = (float*)p;
    cudaGetSymbolAddress(&p, g_proj); pjg = (float*)p;

    copy_k<<<(kBS * kD / 4) / 256, 256>>>(q);

    dim3 ggrid(kD / BN, kBS / BM);   // (8, 16)
    for (int l = 0; l < kL; l++) {
        gemm_tf32<true ><<<ggrid, 256, GEMM_SMEM>>>(xg,  Wq + (size_t)l * kD * kD, bq + l * kD, qhg);
        gemm_tf32<true ><<<ggrid, 256, GEMM_SMEM>>>(xg,  Wv + (size_t)l * kD * kD, bv + l * kD, vhg);
        attn_k<<<kBH * NT16, ATTN_THREADS, ATTN_SMEM>>>(gm + l * kH);
        gemm_tf32<false><<<ggrid, 256, GEMM_SMEM>>>(aog, Wo + (size_t)l * kD * kD, bo + l * kD, pjg);
        ln_k<true ><<<kBS, 256>>>(xg, pjg, lng + l * kD, lnb + l * kD, xg);
    }
    ln_k<false><<<kBS, 256>>>(xg, nullptr, fg, fb, out);
}

// round 8
// speedup vs baseline: 3.0992x; 1.0491x over previous
#include <cuda_runtime.h>
#include <math.h>
#include <stdint.h>

namespace {
constexpr int kBn = 2, kS = 1024, kD = 1024, kH = 16, kDH = 64, kL = 4;
constexpr int kBS = kBn * kS;          // 2048 rows
constexpr int kBH = kBn * kH;          // 32 (b,h) pairs
constexpr int TR = 16;                 // query rows per attention block
constexpr int NT16 = kS / TR;          // 64 tiles per (b,h)
constexpr int SCP = 1028;              // padded score-row stride (stride%32==4)
constexpr int ATTN_THREADS = 256;      // 8 warps
// smem: scores + phase3 reduction buffer + per-warp softmax stats
constexpr int ATTN_SMEM = (TR * SCP + TR * kDH + TR * 8 * 2) * 4;  // 70912 B
// GEMM tiling
constexpr int BM = 128, BN = 128, BK = 32;
constexpr int ASTR = 36, BSTR = 136;   // padded smem strides
constexpr int GEMM_SMEM = (2 * BM * ASTR + 2 * BK * BSTR) * 4;  // 71680 B
}

// Scratch (static device allocations; no runtime allocs)
__device__ float g_x[kBS * kD];
__device__ float g_qh[kBH * kS * kDH];
__device__ float g_vh[kBH * kS * kDH];
__device__ float g_ao[kBS * kD];
__device__ float g_proj[kBS * kD];

// ---------------------------------------------------------------------------
__device__ __forceinline__ uint32_t f2tf(float x) {
    uint32_t r;
    asm("cvt.rna.tf32.f32 %0, %1;" : "=r"(r) : "f"(x));
    return r;
}
__device__ __forceinline__ float sqrt_approx(float x) {
    float r;
    asm("sqrt.approx.f32 %0, %1;" : "=f"(r) : "f"(x));
    return r;
}
__device__ __forceinline__ void mma8(float* d, const uint32_t* a, const uint32_t* b) {
    asm volatile(
        "mma.sync.aligned.m16n8k8.row.col.f32.tf32.tf32.f32 "
        "{%0,%1,%2,%3}, {%4,%5,%6,%7}, {%8,%9}, {%0,%1,%2,%3};\n"
        : "+f"(d[0]), "+f"(d[1]), "+f"(d[2]), "+f"(d[3])
        : "r"(a[0]), "r"(a[1]), "r"(a[2]), "r"(a[3]), "r"(b[0]), "r"(b[1]));
}
// online softmax accumulate
__device__ __forceinline__ void osm(float v, float& m, float& s) {
    if (v > m) { s = s * __expf(m - v) + 1.f; m = v; }
    else       s += __expf(v - m);
}
// merge two (m,s) online-softmax states
__device__ __forceinline__ void osm_merge(float om, float os, float& m, float& s) {
    float nm = fmaxf(m, om);
    s = s * __expf(m - nm) + os * __expf(om - nm);
    m = nm;
}

// ---------------------------------------------------------------------------
__global__ void copy_k(const float* __restrict__ in) {
    int i = blockIdx.x * blockDim.x + threadIdx.x;
    reinterpret_cast<float4*>(g_x)[i] = reinterpret_cast<const float4*>(in)[i];
}

// ---------------------------------------------------------------------------
// Shared GEMM body: C[2048,1024] = A @ W + bias, tf32 mma, cp.async dbuf.
template<bool SCATTER>
__device__ __forceinline__ void gemm_body(const float* __restrict__ A,
                                          const float* __restrict__ W,
                                          const float* __restrict__ bias,
                                          float* __restrict__ C,
                                          int bxx, int byy, float* sm) {
    float* As = sm;
    float* Bs = sm + 2 * BM * ASTR;
    const int tid = threadIdx.x, lane = tid & 31, w = tid >> 5;
    const int gid = lane >> 2, l4 = lane & 3;
    const int warpM = w & 3, warpN = w >> 2;
    const int mbase = byy * BM, nbase = bxx * BN;
    const uint32_t sA = (uint32_t)__cvta_generic_to_shared(As);
    const uint32_t sB = (uint32_t)__cvta_generic_to_shared(Bs);

    auto prefetch = [&](int kt, int buf) {
        #pragma unroll
        for (int i = 0; i < 4; i++) {
            int cid = tid + i * 256;
            int m = cid >> 3, kc = cid & 7;
            uint32_t dst = sA + (uint32_t)((buf * BM * ASTR + m * ASTR + kc * 4) * 4);
            const float* src = A + (size_t)(mbase + m) * kD + kt * BK + kc * 4;
            asm volatile("cp.async.cg.shared.global [%0], [%1], 16;\n" ::"r"(dst), "l"(src));
        }
        #pragma unroll
        for (int i = 0; i < 4; i++) {
            int cid = tid + i * 256;
            int k = cid >> 5, nc = cid & 31;   // full 32 x 128 tile
            uint32_t dst = sB + (uint32_t)((buf * BK * BSTR + k * BSTR + nc * 4) * 4);
            const float* src = W + (size_t)(kt * BK + k) * kD + nbase + nc * 4;
            asm volatile("cp.async.cg.shared.global [%0], [%1], 16;\n" ::"r"(dst), "l"(src));
        }
        asm volatile("cp.async.commit_group;\n");
    };

    float acc[2][8][4] = {};
    prefetch(0, 0);
    const int nK = kD / BK;
    for (int kt = 0; kt < nK; kt++) {
        asm volatile("cp.async.wait_group 0;\n");
        __syncthreads();
        if (kt + 1 < nK) prefetch(kt + 1, (kt + 1) & 1);
        const float* as = As + (kt & 1) * BM * ASTR;
        const float* bs = Bs + (kt & 1) * BK * BSTR;
        #pragma unroll
        for (int ks = 0; ks < 4; ks++) {
            uint32_t af[2][4];
            #pragma unroll
            for (int mt = 0; mt < 2; mt++) {
                int r = warpM * 32 + mt * 16 + gid;
                const float* p = as + r * ASTR + ks * 8 + l4;
                af[mt][0] = f2tf(p[0]);
                af[mt][1] = f2tf(p[8 * ASTR]);
                af[mt][2] = f2tf(p[4]);
                af[mt][3] = f2tf(p[8 * ASTR + 4]);
            }
            #pragma unroll
            for (int nt = 0; nt < 8; nt++) {
                uint32_t bf[2];
                int cn = warpN * 64 + nt * 8 + gid;
                const float* p = bs + (ks * 8 + l4) * BSTR + cn;
                bf[0] = f2tf(p[0]);
                bf[1] = f2tf(p[4 * BSTR]);
                #pragma unroll
                for (int mt = 0; mt < 2; mt++) mma8(acc[mt][nt], af[mt], bf);
            }
        }
        __syncthreads();
    }
    #pragma unroll
    for (int mt = 0; mt < 2; mt++) {
        int r0 = mbase + warpM * 32 + mt * 16 + gid;
        #pragma unroll
        for (int nt = 0; nt < 8; nt++) {
            int cc = nbase + warpN * 64 + nt * 8 + l4 * 2;
            float b0 = bias[cc], b1 = bias[cc + 1];
            float2 u = make_float2(acc[mt][nt][0] + b0, acc[mt][nt][1] + b1);
            float2 v = make_float2(acc[mt][nt][2] + b0, acc[mt][nt][3] + b1);
            if (SCATTER) {
                int bb = r0 / kS, s = r0 - bb * kS;
                int h = cc >> 6, d = cc & 63;
                *(float2*)&C[(((size_t)bb * kH + h) * kS + s) * kDH + d] = u;
                *(float2*)&C[(((size_t)bb * kH + h) * kS + s + 8) * kDH + d] = v;
            } else {
                *(float2*)&C[(size_t)r0 * kD + cc] = u;
                *(float2*)&C[(size_t)(r0 + 8) * kD + cc] = v;
            }
        }
    }
}

// Fused Wq+Wv projections: blockIdx.z selects which GEMM. 256 CTAs fill chip.
__global__ void __launch_bounds__(256) gemm_qv(const float* __restrict__ A,
                                               const float* __restrict__ Wq,
                                               const float* __restrict__ bq,
                                               const float* __restrict__ Wv,
                                               const float* __restrict__ bv,
                                               float* __restrict__ Cq,
                                               float* __restrict__ Cv) {
    extern __shared__ float sm[];
    const float* W = blockIdx.z ? Wv : Wq;
    const float* bias = blockIdx.z ? bv : bq;
    float* C = blockIdx.z ? Cv : Cq;
    gemm_body<true>(A, W, bias, C, blockIdx.x, blockIdx.y, sm);
}

__global__ void __launch_bounds__(256) gemm_o(const float* __restrict__ A,
                                              const float* __restrict__ W,
                                              const float* __restrict__ bias,
                                              float* __restrict__ C) {
    extern __shared__ float sm[];
    gemm_body<false>(A, W, bias, C, blockIdx.x, blockIdx.y, sm);
}

// ---------------------------------------------------------------------------
// Gamma attention, 16 query rows per block, 8 warps, 3 CTAs/SM.
// Softmax-1 stats fused into phase 1; phase 3 split 4 col-groups x 2 halves.
__global__ void __launch_bounds__(ATTN_THREADS, 3) attn_k(const float* __restrict__ gam) {
    extern __shared__ float sc[];                 // [TR][SCP] score rows
    float* red = sc + TR * SCP;                   // [TR][64] phase-3 partials
    float* wstat = red + TR * kDH;                // [TR][8][2] per-warp (m,s)

    const int bx = blockIdx.x;
    const int bh = bx & (kBH - 1);
    const int tile = (NT16 - 1) - (bx >> 5);
    const int h = bh & (kH - 1);
    const int b = bh >> 4;
    const int base = tile * TR;
    const int tid = threadIdx.x, lane = tid & 31, w = tid >> 5;
    const int gid = lane >> 2, l4 = lane & 3;
    const float* qb = g_qh + (size_t)bh * kS * kDH;
    const float* vb = g_vh + (size_t)bh * kS * kDH;
    const int nkt = tile + 1, kLimit = nkt * TR;

    // ---- Phase 1: scores = QK^T / 8 with fused online softmax-1 stats.
    {
        uint32_t qa[8][4];
        #pragma unroll
        for (int ks = 0; ks < 8; ks++) {
            const float* p = qb + (size_t)(base + gid) * kDH + ks * 8 + l4;
            qa[ks][0] = f2tf(p[0]);
            qa[ks][1] = f2tf(p[8 * kDH]);
            qa[ks][2] = f2tf(p[4]);
            qa[ks][3] = f2tf(p[8 * kDH + 4]);
        }
        const int i0 = base + gid, i1 = base + gid + 8;  // this lane's rows
        float m0 = -3.4e38f, s0 = 0.f, m1 = -3.4e38f, s1 = 0.f;
        for (int kt = w; kt < nkt; kt += 8) {
            const float* kp = qb + (size_t)kt * TR * kDH;
            float acc[2][4] = {};
            #pragma unroll
            for (int ks = 0; ks < 8; ks++) {
                #pragma unroll
                for (int nt = 0; nt < 2; nt++) {
                    uint32_t bf[2];
                    const float* p = kp + (size_t)(nt * 8 + gid) * kDH + ks * 8 + l4;
                    bf[0] = f2tf(p[0]);
                    bf[1] = f2tf(p[4]);
                    mma8(acc[nt], qa[ks], bf);
                }
            }
            const bool diag = (kt == tile);
            #pragma unroll
            for (int nt = 0; nt < 2; nt++) {
                int c0 = kt * TR + nt * 8 + l4 * 2;
                float v00 = acc[nt][0] * 0.125f, v01 = acc[nt][1] * 0.125f;
                float v10 = acc[nt][2] * 0.125f, v11 = acc[nt][3] * 0.125f;
                *(float2*)&sc[gid * SCP + c0] = make_float2(v00, v01);
                *(float2*)&sc[(gid + 8) * SCP + c0] = make_float2(v10, v11);
                if (!diag) {            // all cols strictly below both rows
                    osm(v00, m0, s0); osm(v01, m0, s0);
                    osm(v10, m1, s1); osm(v11, m1, s1);
                } else {                // diagonal tile: mask j < i
                    if (c0 < i0)     osm(v00, m0, s0);
                    if (c0 + 1 < i0) osm(v01, m0, s0);
                    if (c0 < i1)     osm(v10, m1, s1);
                    if (c0 + 1 < i1) osm(v11, m1, s1);
                }
            }
        }
        // quad reduce (lanes sharing gid are l4 = 0..3)
        #pragma unroll
        for (int o = 1; o <= 2; o <<= 1) {
            float om = __shfl_xor_sync(~0u, m0, o), os = __shfl_xor_sync(~0u, s0, o);
            osm_merge(om, os, m0, s0);
            om = __shfl_xor_sync(~0u, m1, o); os = __shfl_xor_sync(~0u, s1, o);
            osm_merge(om, os, m1, s1);
        }
        if (l4 == 0) {
            wstat[(gid * 8 + w) * 2] = m0;
            wstat[(gid * 8 + w) * 2 + 1] = s0;
            wstat[((gid + 8) * 8 + w) * 2] = m1;
            wstat[((gid + 8) * 8 + w) * 2 + 1] = s1;
        }
    }
    __syncthreads();

    // ---- Phase 2: combine stats -> scan decay (online stats2) -> finalize.
    {
        const float gm = -fabsf(gam[h]);
        const int i0r = base + w;
        const int i1r = i0r + 8;
        float* row0 = sc + w * SCP;
        float* row1 = sc + (w + 8) * SCP;
        const int nv0 = i0r, nv1 = i1r;   // strict causal: keys j < i

        // combine the 8 per-warp partials for this warp's two rows
        float m0 = -3.4e38f, s0 = 0.f, m1 = -3.4e38f, s1 = 0.f;
        #pragma unroll
        for (int p = 0; p < 8; p++) {
            osm_merge(wstat[(w * 8 + p) * 2], wstat[(w * 8 + p) * 2 + 1], m0, s0);
            osm_merge(wstat[((w + 8) * 8 + p) * 2], wstat[((w + 8) * 8 + p) * 2 + 1], m1, s1);
        }
        const float inv0 = (nv0 > 0) ? 1.f / s0 : 0.f;
        const float inv1 = 1.f / s1;

        // Pass B: warp-scan cumsum of p, apply decay, store s2, online stats2.
        float carry0 = 0.f, carry1 = 0.f;
        float n0 = -3.4e38f, t0 = 0.f, n1 = -3.4e38f, t1 = 0.f;
        for (int c0 = 0; c0 < nv1; c0 += 32) {
            int j = c0 + lane;
            if (c0 < nv0) {
                bool vld = j < nv0;
                float sv = vld ? row0[j] : 0.f;
                float p = vld ? __expf(sv - m0) * inv0 : 0.f;
                #pragma unroll
                for (int o = 1; o < 32; o <<= 1) {
                    float t = __shfl_up_sync(~0u, p, o);
                    if (lane >= o) p += t;
                }
                float cum = p + carry0;
                carry0 = __shfl_sync(~0u, cum, 31);
                if (vld) {
                    float rem = 1.0f - cum;              // disttotal == 1
                    float tt = fmaxf(rem * (float)(i0r - j), 0.f);
                    float eff = fmaxf(__expf(gm * sqrt_approx(tt)), 1e-5f);
                    float s2 = sv * eff;
                    row0[j] = s2;
                    osm(s2, n0, t0);
                }
            }
            {
                bool vld = j < nv1;
                float sv = vld ? row1[j] : 0.f;
                float p = vld ? __expf(sv - m1) * inv1 : 0.f;
                #pragma unroll
                for (int o = 1; o < 32; o <<= 1) {
                    float t = __shfl_up_sync(~0u, p, o);
                    if (lane >= o) p += t;
                }
                float cum = p + carry1;
                carry1 = __shfl_sync(~0u, cum, 31);
                if (vld) {
                    float rem = 1.0f - cum;
                    float tt = fmaxf(rem * (float)(i1r - j), 0.f);
                    float eff = fmaxf(__expf(gm * sqrt_approx(tt)), 1e-5f);
                    float s2 = sv * eff;
                    row1[j] = s2;
                    osm(s2, n1, t1);
                }
            }
        }
        #pragma unroll
        for (int o = 16; o; o >>= 1) {
            float om = __shfl_xor_sync(~0u, n0, o), os = __shfl_xor_sync(~0u, t0, o);
            osm_merge(om, os, n0, t0);
            om = __shfl_xor_sync(~0u, n1, o); os = __shfl_xor_sync(~0u, t1, o);
            osm_merge(om, os, n1, t1);
        }
        // maxout: max(attn) = 1/sum2 exactly => scale = min(sum2,5)/sum2
        const float sf0 = (nv0 > 0) ? fminf(t0, 5.f) / t0 : 0.f;
        const float sf1 = fminf(t1, 5.f) / t1;

        // Pass C: finalize attn values, zero-fill the causal tail.
        for (int j = lane; j < kLimit; j += 32) {
            float o0 = (j < nv0) ? __expf(row0[j] - n0) * sf0 : 0.f;
            float o1 = (j < nv1) ? __expf(row1[j] - n1) * sf1 : 0.f;
            row0[j] = o0;
            row1[j] = o1;
        }
    }
    __syncthreads();

    // ---- Phase 3: out = attn @ V. 4 column groups (16 cols) x 2 kt halves.
    {
        const int cg = w & 3;          // cols [cg*16, cg*16+16)
        const int half = w >> 2;       // kt parity
        float oacc[2][4] = {};
        for (int kt = half; kt < nkt; kt += 2) {
            const float* vp = vb + (size_t)kt * TR * kDH;
            #pragma unroll
            for (int kk = 0; kk < 2; kk++) {
                uint32_t af[4];
                const float* q = sc + gid * SCP + kt * TR + kk * 8 + l4;
                af[0] = f2tf(q[0]);
                af[1] = f2tf(q[8 * SCP]);
                af[2] = f2tf(q[4]);
                af[3] = f2tf(q[8 * SCP + 4]);
                #pragma unroll
                for (int nt = 0; nt < 2; nt++) {
                    uint32_t bf[2];
                    const float* p = vp + (size_t)(kk * 8 + l4) * kDH + cg * 16 + nt * 8 + gid;
                    bf[0] = f2tf(p[0]);
                    bf[1] = f2tf(p[4 * kDH]);
                    mma8(oacc[nt], af, bf);
                }
            }
        }
        if (half == 1) {
            #pragma unroll
            for (int nt = 0; nt < 2; nt++) {
                int cc = cg * 16 + nt * 8 + l4 * 2;
                *(float2*)&red[gid * kDH + cc] = make_float2(oacc[nt][0], oacc[nt][1]);
                *(float2*)&red[(gid + 8) * kDH + cc] = make_float2(oacc[nt][2], oacc[nt][3]);
            }
        }
        __syncthreads();
        if (half == 0) {
            const int i0 = base + gid;
            float* op0 = g_ao + ((size_t)b * kS + i0) * kD + h * kDH;
            #pragma unroll
            for (int nt = 0; nt < 2; nt++) {
                int cc = cg * 16 + nt * 8 + l4 * 2;
                float2 p0 = *(const float2*)&red[gid * kDH + cc];
                float2 p1 = *(const float2*)&red[(gid + 8) * kDH + cc];
                *(float2*)(op0 + cc) =
                    make_float2(oacc[nt][0] + p0.x, oacc[nt][1] + p0.y);
                *(float2*)(op0 + 8 * kD + cc) =
                    make_float2(oacc[nt][2] + p1.x, oacc[nt][3] + p1.y);
            }
        }
    }
}

// ---------------------------------------------------------------------------
template<bool ADD>
__global__ void __launch_bounds__(256) ln_k(const float* __restrict__ X,
                                            const float* __restrict__ Aadd,
                                            const float* __restrict__ g,
                                            const float* __restrict__ bt,
                                            float* __restrict__ out) {
    __shared__ float red[8];
    const int row = blockIdx.x;
    const int tid = threadIdx.x;
    const int lane = tid & 31, w = tid >> 5;
    const float* xr = X + (size_t)row * kD;
    float v[4];
    float s = 0.f;
    #pragma unroll
    for (int t = 0; t < 4; t++) {
        int d = tid + t * 256;
        float val = xr[d];
        if (ADD) val += Aadd[(size_t)row * kD + d];
        v[t] = val;
        s += val;
    }
    #pragma unroll
    for (int o = 16; o; o >>= 1) s += __shfl_xor_sync(~0u, s, o);
    if (lane == 0) red[w] = s;
    __syncthreads();
    float tot = 0.f;
    #pragma unroll
    for (int k = 0; k < 8; k++) tot += red[k];
    const float mu = tot * (1.0f / kD);
    __syncthreads();
    float s2 = 0.f;
    #pragma unroll
    for (int t = 0; t < 4; t++) { float dv = v[t] - mu; s2 += dv * dv; }
    #pragma unroll
    for (int o = 16; o; o >>= 1) s2 += __shfl_xor_sync(~0u, s2, o);
    if (lane == 0) red[w] = s2;
    __syncthreads();
    float tot2 = 0.f;
    #pragma unroll
    for (int k = 0; k < 8; k++) tot2 += red[k];
    const float rs = rsqrtf(tot2 * (1.0f / kD) + 1e-5f);
    #pragma unroll
    for (int t = 0; t < 4; t++) {
        int d = tid + t * 256;
        out[(size_t)row * kD + d] = (v[t] - mu) * rs * g[d] + bt[d];
    }
}

// ---------------------------------------------------------------------------
extern "C" void kernel_launch(void* const* d_in, const int* in_sizes, int n_in,
                              void* d_out, int out_size) {
    (void)in_sizes; (void)n_in; (void)out_size;
    const float* q   = (const float*)d_in[0];
    // d_in[1] = lens (unused in eval mode)
    const float* Wq  = (const float*)d_in[2];
    const float* bq  = (const float*)d_in[3];
    const float* Wv  = (const float*)d_in[4];
    const float* bv  = (const float*)d_in[5];
    const float* Wo  = (const float*)d_in[6];
    const float* bo  = (const float*)d_in[7];
    const float* gm  = (const float*)d_in[8];
    const float* lng = (const float*)d_in[9];
    const float* lnb = (const float*)d_in[10];
    const float* fg  = (const float*)d_in[11];
    const float* fb  = (const float*)d_in[12];
    float* out = (float*)d_out;

    cudaFuncSetAttribute(attn_k, cudaFuncAttributeMaxDynamicSharedMemorySize, ATTN_SMEM);
    cudaFuncSetAttribute(gemm_qv, cudaFuncAttributeMaxDynamicSharedMemorySize, GEMM_SMEM);
    cudaFuncSetAttribute(gemm_o,  cudaFuncAttributeMaxDynamicSharedMemorySize, GEMM_SMEM);

    void* p;
    float *xg, *qhg, *vhg, *aog, *pjg;
    cudaGetSymbolAddress(&p, g_x);    xg  = (float*)p;
    cudaGetSymbolAddress(&p, g_qh);   qhg = (float*)p;
    cudaGetSymbolAddress(&p, g_vh);   vhg = (float*)p;
    cudaGetSymbolAddress(&p, g_ao);   aog = (float*)p;
    cudaGetSymbolAddress(&p, g_proj); pjg = (float*)p;

    copy_k<<<(kBS * kD / 4) / 256, 256>>>(q);

    dim3 gqv(kD / BN, kBS / BM, 2);  // (8, 16, 2) = 256 CTAs
    dim3 ggo(kD / BN, kBS / BM);     // (8, 16)
    for (int l = 0; l < kL; l++) {
        gemm_qv<<<gqv, 256, GEMM_SMEM>>>(xg,
            Wq + (size_t)l * kD * kD, bq + l * kD,
            Wv + (size_t)l * kD * kD, bv + l * kD, qhg, vhg);
        attn_k<<<kBH * NT16, ATTN_THREADS, ATTN_SMEM>>>(gm + l * kH);
        gemm_o<<<ggo, 256, GEMM_SMEM>>>(aog, Wo + (size_t)l * kD * kD, bo + l * kD, pjg);
        ln_k<true ><<<kBS, 256>>>(xg, pjg, lng + l * kD, lnb + l * kD, xg);
    }
    ln_k<false><<<kBS, 256>>>(xg, nullptr, fg, fb, out);
}